// round 3
// baseline (speedup 1.0000x reference)
#include <cuda_runtime.h>

#define NN 50000       // nodes
#define NE 800000      // edges
#define NH 2           // heads
#define ND 32          // dim per head
#define HD 64          // H*D
#define NIN 64         // input dim
#define NEREL 200000   // rel table rows
#define NDREL 32       // rel feature dim

// scratch (static device globals; allocation-free)
__device__ float g_hp[NN * HD];       // target projection [N,H*D]
__device__ float g_esrc[NN * NH];     // per-node src logit
__device__ float g_edst[NN * NH];     // per-node dst logit
__device__ float g_midp[NN * HD];     // mid projection
__device__ float g_gmid[NN * HD];     // midp @ W_edge[:32]
__device__ float g_relp[NEREL * HD];  // rel projection
__device__ float g_grel[NEREL * HD];  // relp @ W_edge[32:]
__device__ float g_ex[NE * NH];       // exp(logit) per edge
__device__ float g_denom[NN * NH];    // softmax denominator per dst
__device__ float g_rst[NN * HD];      // aggregated output

// ---------------------------------------------------------------------------
__global__ void k_zero() {
    int i = blockIdx.x * 256 + threadIdx.x;
    if (i < NN * HD) g_rst[i] = 0.f;
    if (i < NN * NH) g_denom[i] = 0.f;
}

// ---------------------------------------------------------------------------
// hp = h @ W_t + b_t ; e_src/e_dst = sum_d attn * relu(hp)
// block: (64,4) -> 4 nodes per block, thread tx = output column.
// Each warp == one head of one node (tx 0..31 / 32..63 per y-slot).
__global__ void k_proj_target(const float* __restrict__ h,
                              const float* __restrict__ Wt,
                              const float* __restrict__ bt,
                              const float* __restrict__ asrc,
                              const float* __restrict__ adst) {
    __shared__ float Ws[NIN * HD];     // 16KB
    __shared__ float hrow[4][NIN];
    int tx = threadIdx.x, ty = threadIdx.y;
    int lt = ty * 64 + tx;
    for (int i = lt; i < NIN * HD; i += 256) Ws[i] = Wt[i];
    int node = blockIdx.x * 4 + ty;
    hrow[ty][tx] = h[node * NIN + tx];
    __syncthreads();
    float acc = bt[tx];
#pragma unroll
    for (int k = 0; k < NIN; k++) acc = fmaf(hrow[ty][k], Ws[k * HD + tx], acc);
    g_hp[node * HD + tx] = acc;
    float r = fmaxf(acc, 0.f);
    float ps = r * asrc[tx];
    float pd = r * adst[tx];
#pragma unroll
    for (int o = 16; o; o >>= 1) {
        ps += __shfl_xor_sync(0xffffffffu, ps, o);
        pd += __shfl_xor_sync(0xffffffffu, pd, o);
    }
    if ((tx & 31) == 0) {
        int hh = tx >> 5;
        g_esrc[node * NH + hh] = ps;
        g_edst[node * NH + hh] = pd;
    }
}

// ---------------------------------------------------------------------------
// midp = nfeat_mid @ W_mid + b_mid ; gmid = per-head midp @ W_edge[0:32]
__global__ void k_proj_mid(const float* __restrict__ nf,
                           const float* __restrict__ Wm,
                           const float* __restrict__ bm,
                           const float* __restrict__ We) {
    __shared__ float Ws[NIN * HD];   // 16KB
    __shared__ float Wes[ND * ND];   // 4KB : W_edge rows 0..31
    __shared__ float row[4][NIN];
    __shared__ float mp[4][HD];
    int tx = threadIdx.x, ty = threadIdx.y;
    int lt = ty * 64 + tx;
    for (int i = lt; i < NIN * HD; i += 256) Ws[i] = Wm[i];
    for (int i = lt; i < ND * ND; i += 256) Wes[i] = We[i];
    int node = blockIdx.x * 4 + ty;
    row[ty][tx] = nf[node * NIN + tx];
    __syncthreads();
    float acc = bm[tx];
#pragma unroll
    for (int k = 0; k < NIN; k++) acc = fmaf(row[ty][k], Ws[k * HD + tx], acc);
    g_midp[node * HD + tx] = acc;
    mp[ty][tx] = acc;
    __syncthreads();
    int hh = tx >> 5, d = tx & 31;
    float g = 0.f;
#pragma unroll
    for (int k = 0; k < ND; k++) g = fmaf(mp[ty][hh * ND + k], Wes[k * ND + d], g);
    g_gmid[node * HD + tx] = g;
}

// ---------------------------------------------------------------------------
// relp = efeat_rel @ W_rel + b_rel ; grel = per-head relp @ W_edge[32:64]
__global__ void k_proj_rel(const float* __restrict__ ef,
                           const float* __restrict__ Wr,
                           const float* __restrict__ br,
                           const float* __restrict__ We) {
    __shared__ float Ws[NDREL * HD]; // 8KB
    __shared__ float Wes[ND * ND];   // W_edge rows 32..63
    __shared__ float row[4][NDREL];
    __shared__ float mp[4][HD];
    int tx = threadIdx.x, ty = threadIdx.y;
    int lt = ty * 64 + tx;
    for (int i = lt; i < NDREL * HD; i += 256) Ws[i] = Wr[i];
    for (int i = lt; i < ND * ND; i += 256) Wes[i] = We[ND * ND + i];
    int node = blockIdx.x * 4 + ty;
    if (tx < NDREL) row[ty][tx] = ef[node * NDREL + tx];
    __syncthreads();
    float acc = br[tx];
#pragma unroll
    for (int k = 0; k < NDREL; k++) acc = fmaf(row[ty][k], Ws[k * HD + tx], acc);
    g_relp[node * HD + tx] = acc;
    mp[ty][tx] = acc;
    __syncthreads();
    int hh = tx >> 5, d = tx & 31;
    float g = 0.f;
#pragma unroll
    for (int k = 0; k < ND; k++) g = fmaf(mp[ty][hh * ND + k], Wes[k * ND + d], g);
    g_grel[node * HD + tx] = g;
}

// ---------------------------------------------------------------------------
// Per-edge logits + exp + denom atomic. One warp per edge.
// lanes 0..15 gather midp[hn] (float4 each), lanes 16..31 gather relp[he].
__global__ void k_edge_logits(const int* __restrict__ src,
                              const int* __restrict__ dst,
                              const int* __restrict__ hn,
                              const int* __restrict__ he,
                              const float* __restrict__ aedge) {
    int e = blockIdx.x * 8 + (threadIdx.x >> 5);
    if (e >= NE) return;
    int lane = threadIdx.x & 31;
    int nh = hn[e], eh = he[e];
    int c = (lane & 15) * 4;               // column 0..60 within table
    float4 v;
    if (lane < 16) v = *(const float4*)(g_midp + (size_t)nh * HD + c);
    else           v = *(const float4*)(g_relp + (size_t)eh * HD + c);
    int hh = c >> 5;                       // head for these 4 columns
    int off = (c & 31) + ((lane < 16) ? 0 : 32);
    const float* aw = aedge + hh * 64 + off;   // attn_edge flat [H, 2D]
    float p = fmaxf(v.x, 0.f) * aw[0] + fmaxf(v.y, 0.f) * aw[1]
            + fmaxf(v.z, 0.f) * aw[2] + fmaxf(v.w, 0.f) * aw[3];
    float p0 = (hh == 0) ? p : 0.f;
    float p1 = (hh == 1) ? p : 0.f;
#pragma unroll
    for (int o = 16; o; o >>= 1) {
        p0 += __shfl_xor_sync(0xffffffffu, p0, o);
        p1 += __shfl_xor_sync(0xffffffffu, p1, o);
    }
    if (lane == 0) {
        int s = src[e], dn = dst[e];
        float e0 = g_esrc[s * NH]     + g_edst[dn * NH]     + p0;
        float e1 = g_esrc[s * NH + 1] + g_edst[dn * NH + 1] + p1;
        float x0 = __expf(e0);
        float x1 = __expf(e1);
        g_ex[e * NH]     = x0;
        g_ex[e * NH + 1] = x1;
        atomicAdd(&g_denom[dn * NH],     x0);
        atomicAdd(&g_denom[dn * NH + 1], x1);
    }
}

// ---------------------------------------------------------------------------
// Aggregation: rst[dst] += a * (hp[src] + gmid[hn] + grel[he]). Warp per edge,
// lane handles 2 contiguous columns.
__global__ void k_aggregate(const int* __restrict__ src,
                            const int* __restrict__ dst,
                            const int* __restrict__ hn,
                            const int* __restrict__ he) {
    int e = blockIdx.x * 8 + (threadIdx.x >> 5);
    if (e >= NE) return;
    int lane = threadIdx.x & 31;
    int s = src[e], dn = dst[e], nh = hn[e], eh = he[e];
    float2 xv = *(const float2*)(g_ex + (size_t)e * NH);
    float2 dv = *(const float2*)(g_denom + (size_t)dn * NH);
    float a0 = xv.x / dv.x;
    float a1 = xv.y / dv.y;
    int c = lane * 2;
    float2 hv = *(const float2*)(g_hp   + (size_t)s  * HD + c);
    float2 gm = *(const float2*)(g_gmid + (size_t)nh * HD + c);
    float2 gr = *(const float2*)(g_grel + (size_t)eh * HD + c);
    float a = (c < 32) ? a0 : a1;
    float r0 = a * (hv.x + gm.x + gr.x);
    float r1 = a * (hv.y + gm.y + gr.y);
    float* o = g_rst + (size_t)dn * HD + c;
    atomicAdd(o,     r0);
    atomicAdd(o + 1, r1);
}

// ---------------------------------------------------------------------------
// relu(rst + b_edge + hp), then row L2-normalize. Warp per node.
__global__ void k_finalize(const float* __restrict__ be, float* __restrict__ out) {
    int n = blockIdx.x * 8 + (threadIdx.x >> 5);
    if (n >= NN) return;
    int lane = threadIdx.x & 31;
    int c = lane * 2;
    float2 rv = *(const float2*)(g_rst + (size_t)n * HD + c);
    float2 hv = *(const float2*)(g_hp  + (size_t)n * HD + c);
    float r0 = fmaxf(rv.x + be[c & 31] + hv.x, 0.f);
    float r1 = fmaxf(rv.y + be[(c + 1) & 31] + hv.y, 0.f);
    float ss = r0 * r0 + r1 * r1;
#pragma unroll
    for (int o = 16; o; o >>= 1) ss += __shfl_xor_sync(0xffffffffu, ss, o);
    float inv = 1.f / fmaxf(sqrtf(ss), 1e-12f);
    out[n * HD + c]     = r0 * inv;
    out[n * HD + c + 1] = r1 * inv;
}

// ---------------------------------------------------------------------------
extern "C" void kernel_launch(void* const* d_in, const int* in_sizes, int n_in,
                              void* d_out, int out_size) {
    const float* h    = (const float*)d_in[0];
    const float* Wt   = (const float*)d_in[1];
    const float* bt   = (const float*)d_in[2];
    const float* nf   = (const float*)d_in[3];
    const float* Wm   = (const float*)d_in[4];
    const float* bm   = (const float*)d_in[5];
    const float* ef   = (const float*)d_in[6];
    const float* Wr   = (const float*)d_in[7];
    const float* br   = (const float*)d_in[8];
    const float* asrc = (const float*)d_in[9];
    const float* adst = (const float*)d_in[10];
    const float* aedg = (const float*)d_in[11];
    const float* We   = (const float*)d_in[12];
    const float* be   = (const float*)d_in[13];
    const int* src    = (const int*)d_in[14];
    const int* dst    = (const int*)d_in[15];
    const int* hn     = (const int*)d_in[16];
    const int* he     = (const int*)d_in[17];
    float* out = (float*)d_out;

    dim3 b(64, 4);
    k_zero<<<(NN * HD + 255) / 256, 256>>>();
    k_proj_target<<<NN / 4, b>>>(h, Wt, bt, asrc, adst);
    k_proj_mid<<<NN / 4, b>>>(nf, Wm, bm, We);
    k_proj_rel<<<NEREL / 4, b>>>(ef, Wr, br, We);
    k_edge_logits<<<NE / 8, 256>>>(src, dst, hn, he, aedg);
    k_aggregate<<<NE / 8, 256>>>(src, dst, hn, he);
    k_finalize<<<NN / 8, 256>>>(be, out);
}

// round 5
// speedup vs baseline: 1.5567x; 1.5567x over previous
#include <cuda_runtime.h>

#define NN 50000       // nodes
#define NE 800000      // edges
#define NH 2           // heads
#define ND 32          // dim per head
#define HD 64          // H*D
#define NIN 64         // input dim
#define NEREL 200000   // rel table rows
#define NDREL 32       // rel feature dim

#define PROJ_BLOCKS 1184

// scratch (static device globals; allocation-free)
__device__ float g_hp[NN * HD];       // target projection [N,H*D]
__device__ float g_esrc[NN * NH];     // per-node src logit
__device__ float g_edst[NN * NH];     // per-node dst logit
__device__ float g_midp[NN * HD];     // mid projection
__device__ float g_gmid[NN * HD];     // midp @ W_edge[:32]
__device__ float g_relp[NEREL * HD];  // rel projection
__device__ float g_grel[NEREL * HD];  // relp @ W_edge[32:]
__device__ float g_ex[NE * NH];       // exp(logit) per edge
__device__ float g_denom[NN * NH];    // softmax denominator per dst
__device__ float g_rst[NN * HD];      // aggregated output

// packed dual-fp32 FMA: {a0,a1} += {x0,x1} * {w,w}
__device__ __forceinline__ void ffma2(float& a0, float& a1,
                                      float x0, float x1, float w) {
    asm volatile(
        "{\n\t"
        ".reg .b64 A, X, W;\n\t"
        "mov.b64 A, {%0, %1};\n\t"
        "mov.b64 X, {%2, %3};\n\t"
        "mov.b64 W, {%4, %4};\n\t"
        "fma.rn.f32x2 A, X, W, A;\n\t"
        "mov.b64 {%0, %1}, A;\n\t"
        "}"
        : "+f"(a0), "+f"(a1)
        : "f"(x0), "f"(x1), "f"(w));
}

__device__ __forceinline__ void red4(float* p, float x, float y, float z, float w) {
    asm volatile("red.global.add.v4.f32 [%0], {%1, %2, %3, %4};"
                 :: "l"(p), "f"(x), "f"(y), "f"(z), "f"(w) : "memory");
}

// ---------------------------------------------------------------------------
__global__ void k_zero() {
    int i = blockIdx.x * 256 + threadIdx.x;
    if (i < NN * HD) g_rst[i] = 0.f;
    if (i < NN * NH) g_denom[i] = 0.f;
}

// ---------------------------------------------------------------------------
// hp = h @ W_t + b_t ; e_src/e_dst = sum_d attn * relu(hp)
// Persistent blocks: weights in smem once; 16 nodes/tile; 4 nodes/thread.
__global__ void k_proj_target(const float* __restrict__ h,
                              const float* __restrict__ Wt,
                              const float* __restrict__ bt,
                              const float* __restrict__ asrc,
                              const float* __restrict__ adst) {
    __shared__ float Wst[64 * 68];     // transposed, padded: Wst[j*68+k]
    __shared__ float rows[16][64];
    int tx = threadIdx.x, ty = threadIdx.y;
    int lt = ty * 64 + tx;
    for (int i = lt; i < 64 * 64; i += 256) {
        int k = i >> 6, j = i & 63;
        Wst[j * 68 + k] = Wt[i];
    }
    float bcol = bt[tx];
    float as = asrc[tx], ad = adst[tx];

    for (int tile = blockIdx.x; tile < NN / 16; tile += gridDim.x) {
        __syncthreads();
        int nb = tile * 16;
        {
            int idx = lt * 4, r = idx >> 6, c = idx & 63;
            *(float4*)&rows[r][c] = *(const float4*)(h + (size_t)(nb + r) * 64 + c);
        }
        __syncthreads();
        float a0 = bcol, a1 = bcol, a2 = bcol, a3 = bcol;
#pragma unroll
        for (int k4 = 0; k4 < 16; k4++) {
            float4 wv = *(float4*)&Wst[tx * 68 + k4 * 4];
            float4 r0 = *(float4*)&rows[ty][k4 * 4];
            float4 r1 = *(float4*)&rows[ty + 4][k4 * 4];
            float4 r2 = *(float4*)&rows[ty + 8][k4 * 4];
            float4 r3 = *(float4*)&rows[ty + 12][k4 * 4];
            ffma2(a0, a1, r0.x, r1.x, wv.x); ffma2(a2, a3, r2.x, r3.x, wv.x);
            ffma2(a0, a1, r0.y, r1.y, wv.y); ffma2(a2, a3, r2.y, r3.y, wv.y);
            ffma2(a0, a1, r0.z, r1.z, wv.z); ffma2(a2, a3, r2.z, r3.z, wv.z);
            ffma2(a0, a1, r0.w, r1.w, wv.w); ffma2(a2, a3, r2.w, r3.w, wv.w);
        }
        float acc[4] = {a0, a1, a2, a3};
        float ps[4], pd[4];
#pragma unroll
        for (int r = 0; r < 4; r++) {
            int node = nb + r * 4 + ty;
            g_hp[(size_t)node * HD + tx] = acc[r];
            float rl = fmaxf(acc[r], 0.f);
            ps[r] = rl * as;
            pd[r] = rl * ad;
        }
#pragma unroll
        for (int o = 16; o; o >>= 1) {
#pragma unroll
            for (int r = 0; r < 4; r++) {
                ps[r] += __shfl_xor_sync(0xffffffffu, ps[r], o);
                pd[r] += __shfl_xor_sync(0xffffffffu, pd[r], o);
            }
        }
        if ((tx & 31) == 0) {
            int hh = tx >> 5;
#pragma unroll
            for (int r = 0; r < 4; r++) {
                int node = nb + r * 4 + ty;
                g_esrc[node * NH + hh] = ps[r];
                g_edst[node * NH + hh] = pd[r];
            }
        }
    }
}

// ---------------------------------------------------------------------------
// midp = nfeat_mid @ W_mid + b_mid ; gmid = per-head midp @ W_edge[0:32]
__global__ void k_proj_mid(const float* __restrict__ nf,
                           const float* __restrict__ Wm,
                           const float* __restrict__ bm,
                           const float* __restrict__ We) {
    __shared__ float Wst[64 * 68];
    __shared__ float West[32 * 36];    // West[d*36+k] = We[k*32+d], k<32
    __shared__ float rows[16][64];
    __shared__ float mpt[16][64];
    int tx = threadIdx.x, ty = threadIdx.y;
    int lt = ty * 64 + tx;
    for (int i = lt; i < 64 * 64; i += 256) {
        int k = i >> 6, j = i & 63;
        Wst[j * 68 + k] = Wm[i];
    }
    for (int i = lt; i < 32 * 32; i += 256) {
        int k = i >> 5, d = i & 31;
        West[d * 36 + k] = We[k * 32 + d];
    }
    float bcol = bm[tx];
    int d = tx & 31, hh = tx >> 5;

    for (int tile = blockIdx.x; tile < NN / 16; tile += gridDim.x) {
        __syncthreads();
        int nb = tile * 16;
        {
            int idx = lt * 4, r = idx >> 6, c = idx & 63;
            *(float4*)&rows[r][c] = *(const float4*)(nf + (size_t)(nb + r) * 64 + c);
        }
        __syncthreads();
        float a0 = bcol, a1 = bcol, a2 = bcol, a3 = bcol;
#pragma unroll
        for (int k4 = 0; k4 < 16; k4++) {
            float4 wv = *(float4*)&Wst[tx * 68 + k4 * 4];
            float4 r0 = *(float4*)&rows[ty][k4 * 4];
            float4 r1 = *(float4*)&rows[ty + 4][k4 * 4];
            float4 r2 = *(float4*)&rows[ty + 8][k4 * 4];
            float4 r3 = *(float4*)&rows[ty + 12][k4 * 4];
            ffma2(a0, a1, r0.x, r1.x, wv.x); ffma2(a2, a3, r2.x, r3.x, wv.x);
            ffma2(a0, a1, r0.y, r1.y, wv.y); ffma2(a2, a3, r2.y, r3.y, wv.y);
            ffma2(a0, a1, r0.z, r1.z, wv.z); ffma2(a2, a3, r2.z, r3.z, wv.z);
            ffma2(a0, a1, r0.w, r1.w, wv.w); ffma2(a2, a3, r2.w, r3.w, wv.w);
        }
        float acc[4] = {a0, a1, a2, a3};
#pragma unroll
        for (int r = 0; r < 4; r++) {
            int n = r * 4 + ty;
            g_midp[(size_t)(nb + n) * HD + tx] = acc[r];
            mpt[n][tx] = acc[r];
        }
        __syncthreads();
        float g0 = 0.f, g1 = 0.f, g2 = 0.f, g3 = 0.f;
#pragma unroll
        for (int k4 = 0; k4 < 8; k4++) {
            float4 wv = *(float4*)&West[d * 36 + k4 * 4];
            float4 m0 = *(float4*)&mpt[ty][hh * 32 + k4 * 4];
            float4 m1 = *(float4*)&mpt[ty + 4][hh * 32 + k4 * 4];
            float4 m2 = *(float4*)&mpt[ty + 8][hh * 32 + k4 * 4];
            float4 m3 = *(float4*)&mpt[ty + 12][hh * 32 + k4 * 4];
            ffma2(g0, g1, m0.x, m1.x, wv.x); ffma2(g2, g3, m2.x, m3.x, wv.x);
            ffma2(g0, g1, m0.y, m1.y, wv.y); ffma2(g2, g3, m2.y, m3.y, wv.y);
            ffma2(g0, g1, m0.z, m1.z, wv.z); ffma2(g2, g3, m2.z, m3.z, wv.z);
            ffma2(g0, g1, m0.w, m1.w, wv.w); ffma2(g2, g3, m2.w, m3.w, wv.w);
        }
        float gr[4] = {g0, g1, g2, g3};
#pragma unroll
        for (int r = 0; r < 4; r++)
            g_gmid[(size_t)(nb + r * 4 + ty) * HD + tx] = gr[r];
    }
}

// ---------------------------------------------------------------------------
// relp = efeat_rel @ W_rel + b_rel ; grel = per-head relp @ W_edge[32:64]
__global__ void k_proj_rel(const float* __restrict__ ef,
                           const float* __restrict__ Wr,
                           const float* __restrict__ br,
                           const float* __restrict__ We) {
    __shared__ float Wrt[64 * 36];     // Wrt[j*36+k] = Wr[k*64+j], k<32
    __shared__ float West[32 * 36];    // W_edge rows 32..63
    __shared__ float rows[16][32];
    __shared__ float mpt[16][64];
    int tx = threadIdx.x, ty = threadIdx.y;
    int lt = ty * 64 + tx;
    for (int i = lt; i < 32 * 64; i += 256) {
        int k = i >> 6, j = i & 63;
        Wrt[j * 36 + k] = Wr[i];
    }
    for (int i = lt; i < 32 * 32; i += 256) {
        int k = i >> 5, d = i & 31;
        West[d * 36 + k] = We[(k + 32) * 32 + d];
    }
    float bcol = br[tx];
    int d = tx & 31, hh = tx >> 5;

    for (int tile = blockIdx.x; tile < NEREL / 16; tile += gridDim.x) {
        __syncthreads();
        int nb = tile * 16;
        if (lt < 128) {
            int idx = lt * 4, r = idx >> 5, c = idx & 31;
            *(float4*)&rows[r][c] = *(const float4*)(ef + (size_t)(nb + r) * 32 + c);
        }
        __syncthreads();
        float a0 = bcol, a1 = bcol, a2 = bcol, a3 = bcol;
#pragma unroll
        for (int k4 = 0; k4 < 8; k4++) {
            float4 wv = *(float4*)&Wrt[tx * 36 + k4 * 4];
            float4 r0 = *(float4*)&rows[ty][k4 * 4];
            float4 r1 = *(float4*)&rows[ty + 4][k4 * 4];
            float4 r2 = *(float4*)&rows[ty + 8][k4 * 4];
            float4 r3 = *(float4*)&rows[ty + 12][k4 * 4];
            ffma2(a0, a1, r0.x, r1.x, wv.x); ffma2(a2, a3, r2.x, r3.x, wv.x);
            ffma2(a0, a1, r0.y, r1.y, wv.y); ffma2(a2, a3, r2.y, r3.y, wv.y);
            ffma2(a0, a1, r0.z, r1.z, wv.z); ffma2(a2, a3, r2.z, r3.z, wv.z);
            ffma2(a0, a1, r0.w, r1.w, wv.w); ffma2(a2, a3, r2.w, r3.w, wv.w);
        }
        float acc[4] = {a0, a1, a2, a3};
#pragma unroll
        for (int r = 0; r < 4; r++) {
            int n = r * 4 + ty;
            g_relp[(size_t)(nb + n) * HD + tx] = acc[r];
            mpt[n][tx] = acc[r];
        }
        __syncthreads();
        float g0 = 0.f, g1 = 0.f, g2 = 0.f, g3 = 0.f;
#pragma unroll
        for (int k4 = 0; k4 < 8; k4++) {
            float4 wv = *(float4*)&West[d * 36 + k4 * 4];
            float4 m0 = *(float4*)&mpt[ty][hh * 32 + k4 * 4];
            float4 m1 = *(float4*)&mpt[ty + 4][hh * 32 + k4 * 4];
            float4 m2 = *(float4*)&mpt[ty + 8][hh * 32 + k4 * 4];
            float4 m3 = *(float4*)&mpt[ty + 12][hh * 32 + k4 * 4];
            ffma2(g0, g1, m0.x, m1.x, wv.x); ffma2(g2, g3, m2.x, m3.x, wv.x);
            ffma2(g0, g1, m0.y, m1.y, wv.y); ffma2(g2, g3, m2.y, m3.y, wv.y);
            ffma2(g0, g1, m0.z, m1.z, wv.z); ffma2(g2, g3, m2.z, m3.z, wv.z);
            ffma2(g0, g1, m0.w, m1.w, wv.w); ffma2(g2, g3, m2.w, m3.w, wv.w);
        }
        float gr[4] = {g0, g1, g2, g3};
#pragma unroll
        for (int r = 0; r < 4; r++)
            g_grel[(size_t)(nb + r * 4 + ty) * HD + tx] = gr[r];
    }
}

// ---------------------------------------------------------------------------
// Per-edge logits + exp + denom atomic. One warp per edge.
__global__ void k_edge_logits(const int* __restrict__ src,
                              const int* __restrict__ dst,
                              const int* __restrict__ hn,
                              const int* __restrict__ he,
                              const float* __restrict__ aedge) {
    int e = blockIdx.x * 8 + (threadIdx.x >> 5);
    int lane = threadIdx.x & 31;
    int nh = hn[e], eh = he[e];
    int c = (lane & 15) * 4;               // column 0..60 within table
    float4 v;
    if (lane < 16) v = *(const float4*)(g_midp + (size_t)nh * HD + c);
    else           v = *(const float4*)(g_relp + (size_t)eh * HD + c);
    int hh = c >> 5;                       // head for these 4 columns
    int off = (c & 31) + ((lane < 16) ? 0 : 32);
    const float* aw = aedge + hh * 64 + off;   // attn_edge flat [H, 2D]
    float p = fmaxf(v.x, 0.f) * aw[0] + fmaxf(v.y, 0.f) * aw[1]
            + fmaxf(v.z, 0.f) * aw[2] + fmaxf(v.w, 0.f) * aw[3];
    float p0 = (hh == 0) ? p : 0.f;
    float p1 = (hh == 1) ? p : 0.f;
#pragma unroll
    for (int o = 16; o; o >>= 1) {
        p0 += __shfl_xor_sync(0xffffffffu, p0, o);
        p1 += __shfl_xor_sync(0xffffffffu, p1, o);
    }
    if ((lane & 15) == 0) {                // lanes 0 (head0) and 16 (head1)
        int hx = lane >> 4;
        int s = src[e], dn = dst[e];
        float ev = g_esrc[s * NH + hx] + g_edst[dn * NH + hx] + (hx ? p1 : p0);
        float x = __expf(ev);
        g_ex[e * NH + hx] = x;
        atomicAdd(&g_denom[dn * NH + hx], x);
    }
}

// ---------------------------------------------------------------------------
// Aggregation: rst[dst] += a * (hp[src] + gmid[hn] + grel[he]).
// 16 lanes per edge, 2 edges per warp, one red.v4 per lane.
__global__ void k_aggregate(const int* __restrict__ src,
                            const int* __restrict__ dst,
                            const int* __restrict__ hn,
                            const int* __restrict__ he) {
    int warp = blockIdx.x * 8 + (threadIdx.x >> 5);
    int lane = threadIdx.x & 31;
    int sub = lane >> 4;
    int l16 = lane & 15;
    int e = warp * 2 + sub;
    int s = 0, dn = 0, nh = 0, eh = 0;
    float a0 = 0.f, a1 = 0.f;
    if (l16 == 0) {
        s = src[e]; dn = dst[e]; nh = hn[e]; eh = he[e];
        float2 xv = *(const float2*)(g_ex + (size_t)e * NH);
        float2 dv = *(const float2*)(g_denom + (size_t)dn * NH);
        a0 = xv.x / dv.x;
        a1 = xv.y / dv.y;
    }
    int base = sub * 16;
    s  = __shfl_sync(0xffffffffu, s,  base);
    dn = __shfl_sync(0xffffffffu, dn, base);
    nh = __shfl_sync(0xffffffffu, nh, base);
    eh = __shfl_sync(0xffffffffu, eh, base);
    a0 = __shfl_sync(0xffffffffu, a0, base);
    a1 = __shfl_sync(0xffffffffu, a1, base);
    int c = l16 * 4;
    float4 hv = *(const float4*)(g_hp   + (size_t)s  * HD + c);
    float4 gm = *(const float4*)(g_gmid + (size_t)nh * HD + c);
    float4 gr = *(const float4*)(g_grel + (size_t)eh * HD + c);
    float a = (c < 32) ? a0 : a1;
    red4(g_rst + (size_t)dn * HD + c,
         a * (hv.x + gm.x + gr.x),
         a * (hv.y + gm.y + gr.y),
         a * (hv.z + gm.z + gr.z),
         a * (hv.w + gm.w + gr.w));
}

// ---------------------------------------------------------------------------
// relu(rst + b_edge + hp), then row L2-normalize. Warp per node.
__global__ void k_finalize(const float* __restrict__ be, float* __restrict__ out) {
    int n = blockIdx.x * 8 + (threadIdx.x >> 5);
    if (n >= NN) return;
    int lane = threadIdx.x & 31;
    int c = lane * 2;
    float2 rv = *(const float2*)(g_rst + (size_t)n * HD + c);
    float2 hv = *(const float2*)(g_hp  + (size_t)n * HD + c);
    float r0 = fmaxf(rv.x + be[c & 31] + hv.x, 0.f);
    float r1 = fmaxf(rv.y + be[(c + 1) & 31] + hv.y, 0.f);
    float ss = r0 * r0 + r1 * r1;
#pragma unroll
    for (int o = 16; o; o >>= 1) ss += __shfl_xor_sync(0xffffffffu, ss, o);
    float inv = 1.f / fmaxf(sqrtf(ss), 1e-12f);
    out[n * HD + c]     = r0 * inv;
    out[n * HD + c + 1] = r1 * inv;
}

// ---------------------------------------------------------------------------
extern "C" void kernel_launch(void* const* d_in, const int* in_sizes, int n_in,
                              void* d_out, int out_size) {
    const float* h    = (const float*)d_in[0];
    const float* Wt   = (const float*)d_in[1];
    const float* bt   = (const float*)d_in[2];
    const float* nf   = (const float*)d_in[3];
    const float* Wm   = (const float*)d_in[4];
    const float* bm   = (const float*)d_in[5];
    const float* ef   = (const float*)d_in[6];
    const float* Wr   = (const float*)d_in[7];
    const float* br   = (const float*)d_in[8];
    const float* asrc = (const float*)d_in[9];
    const float* adst = (const float*)d_in[10];
    const float* aedg = (const float*)d_in[11];
    const float* We   = (const float*)d_in[12];
    const float* be   = (const float*)d_in[13];
    const int* src    = (const int*)d_in[14];
    const int* dst    = (const int*)d_in[15];
    const int* hn     = (const int*)d_in[16];
    const int* he     = (const int*)d_in[17];
    float* out = (float*)d_out;

    dim3 b(64, 4);
    k_zero<<<(NN * HD + 255) / 256, 256>>>();
    k_proj_target<<<PROJ_BLOCKS, b>>>(h, Wt, bt, asrc, adst);
    k_proj_mid<<<PROJ_BLOCKS, b>>>(nf, Wm, bm, We);
    k_proj_rel<<<PROJ_BLOCKS, b>>>(ef, Wr, br, We);
    k_edge_logits<<<NE / 8, 256>>>(src, dst, hn, he, aedg);
    k_aggregate<<<NE / 16, 256>>>(src, dst, hn, he);
    k_finalize<<<NN / 8, 256>>>(be, out);
}

// round 6
// speedup vs baseline: 2.5491x; 1.6375x over previous
#include <cuda_runtime.h>

#define NN 50000       // nodes
#define NE 800000      // edges
#define NH 2           // heads
#define ND 32          // dim per head
#define HD 64          // H*D
#define NIN 64         // input dim
#define NEREL 200000   // rel table rows
#define NDREL 32       // rel feature dim

#define PROJ_BLOCKS 1184

// scratch (static device globals; allocation-free)
__device__ float g_hp[NN * HD];       // target projection [N,H*D]
__device__ float g_esrc[NN * NH];     // per-node src logit
__device__ float g_edst[NN * NH];     // per-node dst logit
__device__ float g_gmid[NN * HD];     // (nf@Wm+bm) @ We[:32]  per head
__device__ float g_lmid[NN * NH];     // sum attn_edge*relu(midp) per node
__device__ float g_grel[NEREL * HD];  // (ef@Wr+br) @ We[32:]  per head
__device__ float g_lrel[NEREL * NH];  // sum attn_edge*relu(relp) per rel row
__device__ float g_denom[NN * NH];    // softmax denominator per dst
__device__ float g_rst[NN * HD];      // aggregated output (unnormalized)

// fused weights (computed on device)
__device__ float g_Wgm[64 * 64];
__device__ float g_bgm[64];
__device__ float g_Wgr[32 * 64];
__device__ float g_bgr[64];

// packed dual-fp32 FMA: {a0,a1} += {x0,x1} * {w,w}
__device__ __forceinline__ void ffma2(float& a0, float& a1,
                                      float x0, float x1, float w) {
    asm volatile(
        "{\n\t"
        ".reg .b64 A, X, W;\n\t"
        "mov.b64 A, {%0, %1};\n\t"
        "mov.b64 X, {%2, %3};\n\t"
        "mov.b64 W, {%4, %4};\n\t"
        "fma.rn.f32x2 A, X, W, A;\n\t"
        "mov.b64 {%0, %1}, A;\n\t"
        "}"
        : "+f"(a0), "+f"(a1)
        : "f"(x0), "f"(x1), "f"(w));
}

__device__ __forceinline__ void red4(float* p, float x, float y, float z, float w) {
    asm volatile("red.global.add.v4.f32 [%0], {%1, %2, %3, %4};"
                 :: "l"(p), "f"(x), "f"(y), "f"(z), "f"(w) : "memory");
}

// ---------------------------------------------------------------------------
__global__ void k_zero() {
    int i = blockIdx.x * 256 + threadIdx.x;
    if (i < NN * HD) g_rst[i] = 0.f;
    if (i < NN * NH) g_denom[i] = 0.f;
}

// ---------------------------------------------------------------------------
// Fused weights: Wgm = blockdiag-per-head(Wm) @ We[:32], Wgr = Wr @ We[32:]
// grid=8, block=(64,4)
__global__ void k_fuse_weights(const float* __restrict__ Wm,
                               const float* __restrict__ bm,
                               const float* __restrict__ Wr,
                               const float* __restrict__ br,
                               const float* __restrict__ We) {
    __shared__ float WeS[64 * 32];
    int tx = threadIdx.x, ty = threadIdx.y;
    int lt = ty * 64 + tx;
    for (int i = lt; i < 64 * 32; i += 256) WeS[i] = We[i];
    __syncthreads();
    int hh = tx >> 5, d = tx & 31, bid = blockIdx.x;
#pragma unroll
    for (int jj = 0; jj < 2; jj++) {
        int j = bid * 8 + ty + jj * 4;
        float s = 0.f;
#pragma unroll
        for (int k = 0; k < 32; k++)
            s = fmaf(Wm[j * 64 + hh * 32 + k], WeS[k * 32 + d], s);
        g_Wgm[j * 64 + tx] = s;
    }
    {
        int j = bid * 4 + ty;
        float s = 0.f;
#pragma unroll
        for (int k = 0; k < 32; k++)
            s = fmaf(Wr[j * 64 + hh * 32 + k], WeS[(32 + k) * 32 + d], s);
        g_Wgr[j * 64 + tx] = s;
    }
    if (bid == 0 && ty == 0) {
        float s = 0.f, t = 0.f;
#pragma unroll
        for (int k = 0; k < 32; k++) {
            s = fmaf(bm[hh * 32 + k], WeS[k * 32 + d], s);
            t = fmaf(br[hh * 32 + k], WeS[(32 + k) * 32 + d], t);
        }
        g_bgm[tx] = s;
        g_bgr[tx] = t;
    }
}

// ---------------------------------------------------------------------------
// hp = h @ W_t + b_t ; e_src/e_dst = sum_d attn * relu(hp)
__global__ void k_proj_target(const float* __restrict__ h,
                              const float* __restrict__ Wt,
                              const float* __restrict__ bt,
                              const float* __restrict__ asrc,
                              const float* __restrict__ adst) {
    __shared__ float Wst[64 * 68];     // transposed, padded
    __shared__ float rows[16][64];
    int tx = threadIdx.x, ty = threadIdx.y;
    int lt = ty * 64 + tx;
    for (int i = lt; i < 64 * 64; i += 256) {
        int k = i >> 6, j = i & 63;
        Wst[j * 68 + k] = Wt[i];
    }
    float bcol = bt[tx];
    float as = asrc[tx], ad = adst[tx];

    for (int tile = blockIdx.x; tile < NN / 16; tile += gridDim.x) {
        __syncthreads();
        int nb = tile * 16;
        {
            int idx = lt * 4, r = idx >> 6, c = idx & 63;
            *(float4*)&rows[r][c] = *(const float4*)(h + (size_t)(nb + r) * 64 + c);
        }
        __syncthreads();
        float a0 = bcol, a1 = bcol, a2 = bcol, a3 = bcol;
#pragma unroll
        for (int k4 = 0; k4 < 16; k4++) {
            float4 wv = *(float4*)&Wst[tx * 68 + k4 * 4];
            float4 r0 = *(float4*)&rows[ty][k4 * 4];
            float4 r1 = *(float4*)&rows[ty + 4][k4 * 4];
            float4 r2 = *(float4*)&rows[ty + 8][k4 * 4];
            float4 r3 = *(float4*)&rows[ty + 12][k4 * 4];
            ffma2(a0, a1, r0.x, r1.x, wv.x); ffma2(a2, a3, r2.x, r3.x, wv.x);
            ffma2(a0, a1, r0.y, r1.y, wv.y); ffma2(a2, a3, r2.y, r3.y, wv.y);
            ffma2(a0, a1, r0.z, r1.z, wv.z); ffma2(a2, a3, r2.z, r3.z, wv.z);
            ffma2(a0, a1, r0.w, r1.w, wv.w); ffma2(a2, a3, r2.w, r3.w, wv.w);
        }
        float acc[4] = {a0, a1, a2, a3};
        float ps[4], pd[4];
#pragma unroll
        for (int r = 0; r < 4; r++) {
            int node = nb + r * 4 + ty;
            g_hp[(size_t)node * HD + tx] = acc[r];
            float rl = fmaxf(acc[r], 0.f);
            ps[r] = rl * as;
            pd[r] = rl * ad;
        }
#pragma unroll
        for (int o = 16; o; o >>= 1) {
#pragma unroll
            for (int r = 0; r < 4; r++) {
                ps[r] += __shfl_xor_sync(0xffffffffu, ps[r], o);
                pd[r] += __shfl_xor_sync(0xffffffffu, pd[r], o);
            }
        }
        if ((tx & 31) == 0) {
            int hh = tx >> 5;
#pragma unroll
            for (int r = 0; r < 4; r++) {
                int node = nb + r * 4 + ty;
                g_esrc[node * NH + hh] = ps[r];
                g_edst[node * NH + hh] = pd[r];
            }
        }
    }
}

// ---------------------------------------------------------------------------
// Dual GEMM from one smem tile: midp (for lmid scalar) + gmid (fused weights).
__global__ void k_proj_mid(const float* __restrict__ nf,
                           const float* __restrict__ Wm,
                           const float* __restrict__ bm,
                           const float* __restrict__ aedge) {
    __shared__ float Wst[64 * 68];
    __shared__ float Wgt[64 * 68];
    __shared__ float rows[16][64];
    int tx = threadIdx.x, ty = threadIdx.y;
    int lt = ty * 64 + tx;
    for (int i = lt; i < 64 * 64; i += 256) {
        int k = i >> 6, j = i & 63;
        Wst[j * 68 + k] = Wm[i];
        Wgt[j * 68 + k] = g_Wgm[i];
    }
    float bcol = bm[tx], gb = g_bgm[tx];
    int hh = tx >> 5, d = tx & 31;
    float aw = aedge[hh * 64 + d];

    for (int tile = blockIdx.x; tile < NN / 16; tile += gridDim.x) {
        __syncthreads();
        int nb = tile * 16;
        {
            int idx = lt * 4, r = idx >> 6, c = idx & 63;
            *(float4*)&rows[r][c] = *(const float4*)(nf + (size_t)(nb + r) * 64 + c);
        }
        __syncthreads();
        float m0 = bcol, m1 = bcol, m2 = bcol, m3 = bcol;
        float g0 = gb, g1 = gb, g2 = gb, g3 = gb;
#pragma unroll
        for (int k4 = 0; k4 < 16; k4++) {
            float4 wv = *(float4*)&Wst[tx * 68 + k4 * 4];
            float4 gv = *(float4*)&Wgt[tx * 68 + k4 * 4];
            float4 r0 = *(float4*)&rows[ty][k4 * 4];
            float4 r1 = *(float4*)&rows[ty + 4][k4 * 4];
            float4 r2 = *(float4*)&rows[ty + 8][k4 * 4];
            float4 r3 = *(float4*)&rows[ty + 12][k4 * 4];
            ffma2(m0, m1, r0.x, r1.x, wv.x); ffma2(m2, m3, r2.x, r3.x, wv.x);
            ffma2(g0, g1, r0.x, r1.x, gv.x); ffma2(g2, g3, r2.x, r3.x, gv.x);
            ffma2(m0, m1, r0.y, r1.y, wv.y); ffma2(m2, m3, r2.y, r3.y, wv.y);
            ffma2(g0, g1, r0.y, r1.y, gv.y); ffma2(g2, g3, r2.y, r3.y, gv.y);
            ffma2(m0, m1, r0.z, r1.z, wv.z); ffma2(m2, m3, r2.z, r3.z, wv.z);
            ffma2(g0, g1, r0.z, r1.z, gv.z); ffma2(g2, g3, r2.z, r3.z, gv.z);
            ffma2(m0, m1, r0.w, r1.w, wv.w); ffma2(m2, m3, r2.w, r3.w, wv.w);
            ffma2(g0, g1, r0.w, r1.w, gv.w); ffma2(g2, g3, r2.w, r3.w, gv.w);
        }
        float mm[4] = {m0, m1, m2, m3};
        float gg[4] = {g0, g1, g2, g3};
        float lm[4];
#pragma unroll
        for (int r = 0; r < 4; r++) {
            int node = nb + r * 4 + ty;
            g_gmid[(size_t)node * HD + tx] = gg[r];
            lm[r] = fmaxf(mm[r], 0.f) * aw;
        }
#pragma unroll
        for (int o = 16; o; o >>= 1) {
#pragma unroll
            for (int r = 0; r < 4; r++)
                lm[r] += __shfl_xor_sync(0xffffffffu, lm[r], o);
        }
        if ((tx & 31) == 0) {
#pragma unroll
            for (int r = 0; r < 4; r++)
                g_lmid[(nb + r * 4 + ty) * NH + hh] = lm[r];
        }
    }
}

// ---------------------------------------------------------------------------
// Dual GEMM (K=32): relp (for lrel) + grel (fused weights).
__global__ void k_proj_rel(const float* __restrict__ ef,
                           const float* __restrict__ Wr,
                           const float* __restrict__ br,
                           const float* __restrict__ aedge) {
    __shared__ float Wrt[64 * 36];
    __shared__ float Wgt[64 * 36];
    __shared__ float rows[16][32];
    int tx = threadIdx.x, ty = threadIdx.y;
    int lt = ty * 64 + tx;
    for (int i = lt; i < 32 * 64; i += 256) {
        int k = i >> 6, j = i & 63;
        Wrt[j * 36 + k] = Wr[i];
        Wgt[j * 36 + k] = g_Wgr[i];
    }
    float bcol = br[tx], gb = g_bgr[tx];
    int hh = tx >> 5, d = tx & 31;
    float aw = aedge[hh * 64 + 32 + d];

    for (int tile = blockIdx.x; tile < NEREL / 16; tile += gridDim.x) {
        __syncthreads();
        int nb = tile * 16;
        if (lt < 128) {
            int idx = lt * 4, r = idx >> 5, c = idx & 31;
            *(float4*)&rows[r][c] = *(const float4*)(ef + (size_t)(nb + r) * 32 + c);
        }
        __syncthreads();
        float m0 = bcol, m1 = bcol, m2 = bcol, m3 = bcol;
        float g0 = gb, g1 = gb, g2 = gb, g3 = gb;
#pragma unroll
        for (int k4 = 0; k4 < 8; k4++) {
            float4 wv = *(float4*)&Wrt[tx * 36 + k4 * 4];
            float4 gv = *(float4*)&Wgt[tx * 36 + k4 * 4];
            float4 r0 = *(float4*)&rows[ty][k4 * 4];
            float4 r1 = *(float4*)&rows[ty + 4][k4 * 4];
            float4 r2 = *(float4*)&rows[ty + 8][k4 * 4];
            float4 r3 = *(float4*)&rows[ty + 12][k4 * 4];
            ffma2(m0, m1, r0.x, r1.x, wv.x); ffma2(m2, m3, r2.x, r3.x, wv.x);
            ffma2(g0, g1, r0.x, r1.x, gv.x); ffma2(g2, g3, r2.x, r3.x, gv.x);
            ffma2(m0, m1, r0.y, r1.y, wv.y); ffma2(m2, m3, r2.y, r3.y, wv.y);
            ffma2(g0, g1, r0.y, r1.y, gv.y); ffma2(g2, g3, r2.y, r3.y, gv.y);
            ffma2(m0, m1, r0.z, r1.z, wv.z); ffma2(m2, m3, r2.z, r3.z, wv.z);
            ffma2(g0, g1, r0.z, r1.z, gv.z); ffma2(g2, g3, r2.z, r3.z, gv.z);
            ffma2(m0, m1, r0.w, r1.w, wv.w); ffma2(m2, m3, r2.w, r3.w, wv.w);
            ffma2(g0, g1, r0.w, r1.w, gv.w); ffma2(g2, g3, r2.w, r3.w, gv.w);
        }
        float mm[4] = {m0, m1, m2, m3};
        float gg[4] = {g0, g1, g2, g3};
        float lm[4];
#pragma unroll
        for (int r = 0; r < 4; r++) {
            int node = nb + r * 4 + ty;
            g_grel[(size_t)node * HD + tx] = gg[r];
            lm[r] = fmaxf(mm[r], 0.f) * aw;
        }
#pragma unroll
        for (int o = 16; o; o >>= 1) {
#pragma unroll
            for (int r = 0; r < 4; r++)
                lm[r] += __shfl_xor_sync(0xffffffffu, lm[r], o);
        }
        if ((tx & 31) == 0) {
#pragma unroll
            for (int r = 0; r < 4; r++)
                g_lrel[(nb + r * 4 + ty) * NH + hh] = lm[r];
        }
    }
}

// ---------------------------------------------------------------------------
// Fused edge pass: logit from per-node scalars, exp, denom atomic, and
// UNNORMALIZED weighted aggregation (normalize in finalize).
// 16 lanes per edge, 2 edges per warp.
__global__ void k_edge(const int* __restrict__ src,
                       const int* __restrict__ dst,
                       const int* __restrict__ hn,
                       const int* __restrict__ he) {
    int warp = blockIdx.x * 8 + (threadIdx.x >> 5);
    int lane = threadIdx.x & 31;
    int sub = lane >> 4;
    int l16 = lane & 15;
    int e = warp * 2 + sub;
    int s = 0, dn = 0, nh = 0, eh = 0;
    float ex0 = 0.f, ex1 = 0.f;
    if (l16 == 0) {
        s = src[e]; dn = dst[e]; nh = hn[e]; eh = he[e];
        float2 es = *(const float2*)(g_esrc + (size_t)s * NH);
        float2 ed = *(const float2*)(g_edst + (size_t)dn * NH);
        float2 lm = *(const float2*)(g_lmid + (size_t)nh * NH);
        float2 lr = *(const float2*)(g_lrel + (size_t)eh * NH);
        ex0 = __expf(es.x + ed.x + lm.x + lr.x);
        ex1 = __expf(es.y + ed.y + lm.y + lr.y);
        atomicAdd(&g_denom[dn * NH],     ex0);
        atomicAdd(&g_denom[dn * NH + 1], ex1);
    }
    int base = sub * 16;
    s   = __shfl_sync(0xffffffffu, s,   base);
    dn  = __shfl_sync(0xffffffffu, dn,  base);
    nh  = __shfl_sync(0xffffffffu, nh,  base);
    eh  = __shfl_sync(0xffffffffu, eh,  base);
    ex0 = __shfl_sync(0xffffffffu, ex0, base);
    ex1 = __shfl_sync(0xffffffffu, ex1, base);
    int c = l16 * 4;
    float4 hv = *(const float4*)(g_hp   + (size_t)s  * HD + c);
    float4 gm = *(const float4*)(g_gmid + (size_t)nh * HD + c);
    float4 gr = *(const float4*)(g_grel + (size_t)eh * HD + c);
    float a = (c < 32) ? ex0 : ex1;
    red4(g_rst + (size_t)dn * HD + c,
         a * (hv.x + gm.x + gr.x),
         a * (hv.y + gm.y + gr.y),
         a * (hv.z + gm.z + gr.z),
         a * (hv.w + gm.w + gr.w));
}

// ---------------------------------------------------------------------------
// relu(rst/denom + b_edge + hp), then row L2-normalize. Warp per node.
__global__ void k_finalize(const float* __restrict__ be, float* __restrict__ out) {
    int n = blockIdx.x * 8 + (threadIdx.x >> 5);
    if (n >= NN) return;
    int lane = threadIdx.x & 31;
    int c = lane * 2;
    int hh = lane >> 4;
    float dnm = g_denom[n * NH + hh];
    float inv = (dnm > 0.f) ? 1.f / dnm : 0.f;
    float2 rv = *(const float2*)(g_rst + (size_t)n * HD + c);
    float2 hv = *(const float2*)(g_hp  + (size_t)n * HD + c);
    float r0 = fmaxf(rv.x * inv + be[c & 31] + hv.x, 0.f);
    float r1 = fmaxf(rv.y * inv + be[(c + 1) & 31] + hv.y, 0.f);
    float ss = r0 * r0 + r1 * r1;
#pragma unroll
    for (int o = 16; o; o >>= 1) ss += __shfl_xor_sync(0xffffffffu, ss, o);
    float nrm = 1.f / fmaxf(sqrtf(ss), 1e-12f);
    out[n * HD + c]     = r0 * nrm;
    out[n * HD + c + 1] = r1 * nrm;
}

// ---------------------------------------------------------------------------
extern "C" void kernel_launch(void* const* d_in, const int* in_sizes, int n_in,
                              void* d_out, int out_size) {
    const float* h    = (const float*)d_in[0];
    const float* Wt   = (const float*)d_in[1];
    const float* bt   = (const float*)d_in[2];
    const float* nf   = (const float*)d_in[3];
    const float* Wm   = (const float*)d_in[4];
    const float* bm   = (const float*)d_in[5];
    const float* ef   = (const float*)d_in[6];
    const float* Wr   = (const float*)d_in[7];
    const float* br   = (const float*)d_in[8];
    const float* asrc = (const float*)d_in[9];
    const float* adst = (const float*)d_in[10];
    const float* aedg = (const float*)d_in[11];
    const float* We   = (const float*)d_in[12];
    const float* be   = (const float*)d_in[13];
    const int* src    = (const int*)d_in[14];
    const int* dst    = (const int*)d_in[15];
    const int* hn     = (const int*)d_in[16];
    const int* he     = (const int*)d_in[17];
    float* out = (float*)d_out;

    dim3 b(64, 4);
    k_zero<<<(NN * HD + 255) / 256, 256>>>();
    k_fuse_weights<<<8, b>>>(Wm, bm, Wr, br, We);
    k_proj_target<<<PROJ_BLOCKS, b>>>(h, Wt, bt, asrc, adst);
    k_proj_mid<<<PROJ_BLOCKS, b>>>(nf, Wm, bm, aedg);
    k_proj_rel<<<PROJ_BLOCKS, b>>>(ef, Wr, br, aedg);
    k_edge<<<NE / 16, 256>>>(src, dst, hn, he);
    k_finalize<<<NN / 8, 256>>>(be, out);
}